// round 1
// baseline (speedup 1.0000x reference)
#include <cuda_runtime.h>
#include <cuda_fp16.h>
#include <cstdint>

#define NB 8
#define NC 128
#define NN 4096   // w*h

// Scratch (device globals: the sanctioned allocation-free scratch mechanism)
__device__ __half g_h[(size_t)NB * NC * NN];   // fp16 copy of x:  [b][c][i]
__device__ __half g_s[(size_t)NB * NN * NN];   // scores, then attn in-place: [b][i][j]

// ---------------------------------------------------------------------------
// K0: fp32 -> fp16 convert
// ---------------------------------------------------------------------------
__global__ void k_convert(const float* __restrict__ x) {
    size_t i = (size_t)blockIdx.x * blockDim.x + threadIdx.x;
    const size_t n = (size_t)NB * NC * NN;
    if (i < n) g_h[i] = __float2half(x[i]);
}

// ---------------------------------------------------------------------------
// mma.sync m16n8k16 fp16 -> fp32
// ---------------------------------------------------------------------------
__device__ __forceinline__ void mma16816(float* d, const uint32_t* a, const uint32_t* b) {
    asm volatile(
        "mma.sync.aligned.m16n8k16.row.col.f32.f16.f16.f32 "
        "{%0,%1,%2,%3}, {%4,%5,%6,%7}, {%8,%9}, {%0,%1,%2,%3};"
        : "+f"(d[0]), "+f"(d[1]), "+f"(d[2]), "+f"(d[3])
        : "r"(a[0]), "r"(a[1]), "r"(a[2]), "r"(a[3]), "r"(b[0]), "r"(b[1]));
}

// ---------------------------------------------------------------------------
// K1: S[b,i,j] = sum_c h[b,c,i] * h[b,c,j]
// CTA tile 128x128, K=128 in 2 chunks of 64, 8 warps (2x4), warp tile 64x32.
// Smem layout As[i][c], Bs[j][c] (row-major MxK / N-major B) -> all fragment
// loads are plain aligned 32-bit LDS (no ldmatrix needed).
// ---------------------------------------------------------------------------
__global__ __launch_bounds__(256) void k_scores() {
    __shared__ __half As[128][66];
    __shared__ __half Bs[128][66];

    const int b  = blockIdx.z;
    const int i0 = blockIdx.y * 128;
    const int j0 = blockIdx.x * 128;
    const int tid = threadIdx.x;
    const int w = tid >> 5, lane = tid & 31;
    const int wy = w >> 2, wx = w & 3;        // wy: 0..1 (i), wx: 0..3 (j)
    const int qr = lane >> 2, qc = lane & 3;

    const __half* hb = g_h + (size_t)b * NC * NN;

    float acc[4][4][4];
#pragma unroll
    for (int mi = 0; mi < 4; mi++)
#pragma unroll
        for (int nj = 0; nj < 4; nj++)
#pragma unroll
            for (int r = 0; r < 4; r++) acc[mi][nj][r] = 0.f;

    for (int c0 = 0; c0 < NC; c0 += 64) {
        // transpose-load: As[i][c] = h[c0+c][i0+i], Bs[j][c] = h[c0+c][j0+j]
        for (int idx = tid; idx < 128 * 64; idx += 256) {
            int i = idx & 127, c = idx >> 7;
            As[i][c] = hb[(size_t)(c0 + c) * NN + i0 + i];
            Bs[i][c] = hb[(size_t)(c0 + c) * NN + j0 + i];
        }
        __syncthreads();

#pragma unroll
        for (int kk = 0; kk < 64; kk += 16) {
            uint32_t afr[4][4], bfr[4][2];
#pragma unroll
            for (int mi = 0; mi < 4; mi++) {
                int r = wy * 64 + mi * 16 + qr;
                afr[mi][0] = *(const uint32_t*)&As[r][kk + qc * 2];
                afr[mi][1] = *(const uint32_t*)&As[r + 8][kk + qc * 2];
                afr[mi][2] = *(const uint32_t*)&As[r][kk + qc * 2 + 8];
                afr[mi][3] = *(const uint32_t*)&As[r + 8][kk + qc * 2 + 8];
            }
#pragma unroll
            for (int nj = 0; nj < 4; nj++) {
                int rj = wx * 32 + nj * 8 + qr;
                bfr[nj][0] = *(const uint32_t*)&Bs[rj][kk + qc * 2];
                bfr[nj][1] = *(const uint32_t*)&Bs[rj][kk + qc * 2 + 8];
            }
#pragma unroll
            for (int mi = 0; mi < 4; mi++)
#pragma unroll
                for (int nj = 0; nj < 4; nj++)
                    mma16816(acc[mi][nj], afr[mi], bfr[nj]);
        }
        __syncthreads();
    }

    // epilogue: fp16 store of scores
    __half* sb = g_s + (size_t)b * NN * NN;
#pragma unroll
    for (int mi = 0; mi < 4; mi++) {
#pragma unroll
        for (int nj = 0; nj < 4; nj++) {
            int r = i0 + wy * 64 + mi * 16 + qr;
            int cj = j0 + wx * 32 + nj * 8 + qc * 2;
            __half2 v01 = __floats2half2_rn(acc[mi][nj][0], acc[mi][nj][1]);
            __half2 v23 = __floats2half2_rn(acc[mi][nj][2], acc[mi][nj][3]);
            *(__half2*)&sb[(size_t)r * NN + cj] = v01;
            *(__half2*)&sb[(size_t)(r + 8) * NN + cj] = v23;
        }
    }
}

// ---------------------------------------------------------------------------
// K2: column softmax over i (axis 1). One thread per column j.
// Pass 1: online max + sum-exp. Pass 2: write normalized attn in-place (fp16).
// ---------------------------------------------------------------------------
__global__ __launch_bounds__(128) void k_softmax() {
    const int b = blockIdx.y;
    const int j = blockIdx.x * 128 + threadIdx.x;
    __half* sb = g_s + (size_t)b * NN * NN + j;

    float m = -1e30f, l = 0.f;
#pragma unroll 8
    for (int i = 0; i < NN; i++) {
        float s = __half2float(sb[(size_t)i * NN]);
        float mn = fmaxf(m, s);
        l = l * __expf(m - mn) + __expf(s - mn);
        m = mn;
    }
    float inv = 1.f / l;
#pragma unroll 8
    for (int i = 0; i < NN; i++) {
        float s = __half2float(sb[(size_t)i * NN]);
        sb[(size_t)i * NN] = __float2half(__expf(s - m) * inv);
    }
}

// ---------------------------------------------------------------------------
// K3: ai[b,c,j] = sum_i h[b,c,i] * attn[b,i,j];  out = x + 0.002*ai
// CTA: full M=128 (c) x 128 j-tile, K=4096 in chunks of 32.
// As[c][i] (row-major MxK), Bs[j][i] (transposed on load -> N-major).
// ---------------------------------------------------------------------------
__global__ __launch_bounds__(256) void k_av(const float* __restrict__ x,
                                            float* __restrict__ out) {
    __shared__ __half As[128][34];   // [c][ik]
    __shared__ __half Bs[128][34];   // [j][ik]

    const int b  = blockIdx.y;
    const int j0 = blockIdx.x * 128;
    const int tid = threadIdx.x;
    const int w = tid >> 5, lane = tid & 31;
    const int wy = w >> 2, wx = w & 3;
    const int qr = lane >> 2, qc = lane & 3;

    const __half* hb = g_h + (size_t)b * NC * NN;
    const __half* sb = g_s + (size_t)b * NN * NN;

    float acc[4][4][4];
#pragma unroll
    for (int mi = 0; mi < 4; mi++)
#pragma unroll
        for (int nj = 0; nj < 4; nj++)
#pragma unroll
            for (int r = 0; r < 4; r++) acc[mi][nj][r] = 0.f;

    for (int k0 = 0; k0 < NN; k0 += 32) {
        // As[c][i] = h[c][k0+i]
        for (int idx = tid; idx < 128 * 32; idx += 256) {
            int i = idx & 31, c = idx >> 5;
            As[c][i] = hb[(size_t)c * NN + k0 + i];
        }
        // Bs[j][i] = attn[k0+i][j0+j]  (transpose on load)
        for (int idx = tid; idx < 32 * 128; idx += 256) {
            int j = idx & 127, i = idx >> 7;
            Bs[j][i] = sb[(size_t)(k0 + i) * NN + j0 + j];
        }
        __syncthreads();

#pragma unroll
        for (int kk = 0; kk < 32; kk += 16) {
            uint32_t afr[4][4], bfr[4][2];
#pragma unroll
            for (int mi = 0; mi < 4; mi++) {
                int r = wy * 64 + mi * 16 + qr;
                afr[mi][0] = *(const uint32_t*)&As[r][kk + qc * 2];
                afr[mi][1] = *(const uint32_t*)&As[r + 8][kk + qc * 2];
                afr[mi][2] = *(const uint32_t*)&As[r][kk + qc * 2 + 8];
                afr[mi][3] = *(const uint32_t*)&As[r + 8][kk + qc * 2 + 8];
            }
#pragma unroll
            for (int nj = 0; nj < 4; nj++) {
                int rj = wx * 32 + nj * 8 + qr;
                bfr[nj][0] = *(const uint32_t*)&Bs[rj][kk + qc * 2];
                bfr[nj][1] = *(const uint32_t*)&Bs[rj][kk + qc * 2 + 8];
            }
#pragma unroll
            for (int mi = 0; mi < 4; mi++)
#pragma unroll
                for (int nj = 0; nj < 4; nj++)
                    mma16816(acc[mi][nj], afr[mi], bfr[nj]);
        }
        __syncthreads();
    }

    // epilogue: out = x + 0.002 * ai
#pragma unroll
    for (int mi = 0; mi < 4; mi++) {
#pragma unroll
        for (int nj = 0; nj < 4; nj++) {
            int c  = wy * 64 + mi * 16 + qr;
            int cj = j0 + wx * 32 + nj * 8 + qc * 2;
            size_t o0 = ((size_t)b * NC + c) * NN + cj;
            size_t o1 = ((size_t)b * NC + c + 8) * NN + cj;
            out[o0]     = x[o0]     + 0.002f * acc[mi][nj][0];
            out[o0 + 1] = x[o0 + 1] + 0.002f * acc[mi][nj][1];
            out[o1]     = x[o1]     + 0.002f * acc[mi][nj][2];
            out[o1 + 1] = x[o1 + 1] + 0.002f * acc[mi][nj][3];
        }
    }
}

// ---------------------------------------------------------------------------
extern "C" void kernel_launch(void* const* d_in, const int* in_sizes, int n_in,
                              void* d_out, int out_size) {
    const float* x = (const float*)d_in[0];
    float* out = (float*)d_out;

    // K0: convert
    {
        size_t n = (size_t)NB * NC * NN;
        int threads = 256;
        int blocks = (int)((n + threads - 1) / threads);
        k_convert<<<blocks, threads>>>(x);
    }
    // K1: scores = F^T F
    {
        dim3 grid(NN / 128, NN / 128, NB);
        k_scores<<<grid, 256>>>();
    }
    // K2: column softmax
    {
        dim3 grid(NN / 128, NB);
        k_softmax<<<grid, 128>>>();
    }
    // K3: ai = F @ attn, residual epilogue
    {
        dim3 grid(NN / 128, NB);
        k_av<<<grid, 256>>>(x, out);
    }
}

// round 2
// speedup vs baseline: 1.0004x; 1.0004x over previous
#include <cuda_runtime.h>
#include <cuda_fp16.h>
#include <cstdint>

#define NB 8
#define NC 128
#define NN 4096   // w*h

// Scratch (device globals: the sanctioned allocation-free scratch mechanism)
__device__ __half g_h[(size_t)NB * NC * NN];   // fp16 copy of x:  [b][c][i]
__device__ __half g_s[(size_t)NB * NN * NN];   // scores, then attn in-place: [b][i][j]

// ---------------------------------------------------------------------------
// K0: fp32 -> fp16 convert
// ---------------------------------------------------------------------------
__global__ void k_convert(const float* __restrict__ x) {
    size_t i = (size_t)blockIdx.x * blockDim.x + threadIdx.x;
    const size_t n = (size_t)NB * NC * NN;
    if (i < n) g_h[i] = __float2half(x[i]);
}

// ---------------------------------------------------------------------------
// mma.sync m16n8k16 fp16 -> fp32
// ---------------------------------------------------------------------------
__device__ __forceinline__ void mma16816(float* d, const uint32_t* a, const uint32_t* b) {
    asm volatile(
        "mma.sync.aligned.m16n8k16.row.col.f32.f16.f16.f32 "
        "{%0,%1,%2,%3}, {%4,%5,%6,%7}, {%8,%9}, {%0,%1,%2,%3};"
        : "+f"(d[0]), "+f"(d[1]), "+f"(d[2]), "+f"(d[3])
        : "r"(a[0]), "r"(a[1]), "r"(a[2]), "r"(a[3]), "r"(b[0]), "r"(b[1]));
}

// ---------------------------------------------------------------------------
// K1: S[b,i,j] = sum_c h[b,c,i] * h[b,c,j]
// CTA tile 128x128, K=128 in 2 chunks of 64, 8 warps (2x4), warp tile 64x32.
// Smem layout As[i][c], Bs[j][c] (row-major MxK / N-major B) -> all fragment
// loads are plain aligned 32-bit LDS (no ldmatrix needed).
// ---------------------------------------------------------------------------
__global__ __launch_bounds__(256) void k_scores() {
    __shared__ __half As[128][66];
    __shared__ __half Bs[128][66];

    const int b  = blockIdx.z;
    const int i0 = blockIdx.y * 128;
    const int j0 = blockIdx.x * 128;
    const int tid = threadIdx.x;
    const int w = tid >> 5, lane = tid & 31;
    const int wy = w >> 2, wx = w & 3;        // wy: 0..1 (i), wx: 0..3 (j)
    const int qr = lane >> 2, qc = lane & 3;

    const __half* hb = g_h + (size_t)b * NC * NN;

    float acc[4][4][4];
#pragma unroll
    for (int mi = 0; mi < 4; mi++)
#pragma unroll
        for (int nj = 0; nj < 4; nj++)
#pragma unroll
            for (int r = 0; r < 4; r++) acc[mi][nj][r] = 0.f;

    for (int c0 = 0; c0 < NC; c0 += 64) {
        // transpose-load: As[i][c] = h[c0+c][i0+i], Bs[j][c] = h[c0+c][j0+j]
        for (int idx = tid; idx < 128 * 64; idx += 256) {
            int i = idx & 127, c = idx >> 7;
            As[i][c] = hb[(size_t)(c0 + c) * NN + i0 + i];
            Bs[i][c] = hb[(size_t)(c0 + c) * NN + j0 + i];
        }
        __syncthreads();

#pragma unroll
        for (int kk = 0; kk < 64; kk += 16) {
            uint32_t afr[4][4], bfr[4][2];
#pragma unroll
            for (int mi = 0; mi < 4; mi++) {
                int r = wy * 64 + mi * 16 + qr;
                afr[mi][0] = *(const uint32_t*)&As[r][kk + qc * 2];
                afr[mi][1] = *(const uint32_t*)&As[r + 8][kk + qc * 2];
                afr[mi][2] = *(const uint32_t*)&As[r][kk + qc * 2 + 8];
                afr[mi][3] = *(const uint32_t*)&As[r + 8][kk + qc * 2 + 8];
            }
#pragma unroll
            for (int nj = 0; nj < 4; nj++) {
                int rj = wx * 32 + nj * 8 + qr;
                bfr[nj][0] = *(const uint32_t*)&Bs[rj][kk + qc * 2];
                bfr[nj][1] = *(const uint32_t*)&Bs[rj][kk + qc * 2 + 8];
            }
#pragma unroll
            for (int mi = 0; mi < 4; mi++)
#pragma unroll
                for (int nj = 0; nj < 4; nj++)
                    mma16816(acc[mi][nj], afr[mi], bfr[nj]);
        }
        __syncthreads();
    }

    // epilogue: fp16 store of scores
    __half* sb = g_s + (size_t)b * NN * NN;
#pragma unroll
    for (int mi = 0; mi < 4; mi++) {
#pragma unroll
        for (int nj = 0; nj < 4; nj++) {
            int r = i0 + wy * 64 + mi * 16 + qr;
            int cj = j0 + wx * 32 + nj * 8 + qc * 2;
            __half2 v01 = __floats2half2_rn(acc[mi][nj][0], acc[mi][nj][1]);
            __half2 v23 = __floats2half2_rn(acc[mi][nj][2], acc[mi][nj][3]);
            *(__half2*)&sb[(size_t)r * NN + cj] = v01;
            *(__half2*)&sb[(size_t)(r + 8) * NN + cj] = v23;
        }
    }
}

// ---------------------------------------------------------------------------
// K2: column softmax over i (axis 1). One thread per column j.
// Pass 1: online max + sum-exp. Pass 2: write normalized attn in-place (fp16).
// ---------------------------------------------------------------------------
__global__ __launch_bounds__(128) void k_softmax() {
    const int b = blockIdx.y;
    const int j = blockIdx.x * 128 + threadIdx.x;
    __half* sb = g_s + (size_t)b * NN * NN + j;

    float m = -1e30f, l = 0.f;
#pragma unroll 8
    for (int i = 0; i < NN; i++) {
        float s = __half2float(sb[(size_t)i * NN]);
        float mn = fmaxf(m, s);
        l = l * __expf(m - mn) + __expf(s - mn);
        m = mn;
    }
    float inv = 1.f / l;
#pragma unroll 8
    for (int i = 0; i < NN; i++) {
        float s = __half2float(sb[(size_t)i * NN]);
        sb[(size_t)i * NN] = __float2half(__expf(s - m) * inv);
    }
}

// ---------------------------------------------------------------------------
// K3: ai[b,c,j] = sum_i h[b,c,i] * attn[b,i,j];  out = x + 0.002*ai
// CTA: full M=128 (c) x 128 j-tile, K=4096 in chunks of 32.
// As[c][i] (row-major MxK), Bs[j][i] (transposed on load -> N-major).
// ---------------------------------------------------------------------------
__global__ __launch_bounds__(256) void k_av(const float* __restrict__ x,
                                            float* __restrict__ out) {
    __shared__ __half As[128][34];   // [c][ik]
    __shared__ __half Bs[128][34];   // [j][ik]

    const int b  = blockIdx.y;
    const int j0 = blockIdx.x * 128;
    const int tid = threadIdx.x;
    const int w = tid >> 5, lane = tid & 31;
    const int wy = w >> 2, wx = w & 3;
    const int qr = lane >> 2, qc = lane & 3;

    const __half* hb = g_h + (size_t)b * NC * NN;
    const __half* sb = g_s + (size_t)b * NN * NN;

    float acc[4][4][4];
#pragma unroll
    for (int mi = 0; mi < 4; mi++)
#pragma unroll
        for (int nj = 0; nj < 4; nj++)
#pragma unroll
            for (int r = 0; r < 4; r++) acc[mi][nj][r] = 0.f;

    for (int k0 = 0; k0 < NN; k0 += 32) {
        // As[c][i] = h[c][k0+i]
        for (int idx = tid; idx < 128 * 32; idx += 256) {
            int i = idx & 31, c = idx >> 5;
            As[c][i] = hb[(size_t)c * NN + k0 + i];
        }
        // Bs[j][i] = attn[k0+i][j0+j]  (transpose on load)
        for (int idx = tid; idx < 32 * 128; idx += 256) {
            int j = idx & 127, i = idx >> 7;
            Bs[j][i] = sb[(size_t)(k0 + i) * NN + j0 + j];
        }
        __syncthreads();

#pragma unroll
        for (int kk = 0; kk < 32; kk += 16) {
            uint32_t afr[4][4], bfr[4][2];
#pragma unroll
            for (int mi = 0; mi < 4; mi++) {
                int r = wy * 64 + mi * 16 + qr;
                afr[mi][0] = *(const uint32_t*)&As[r][kk + qc * 2];
                afr[mi][1] = *(const uint32_t*)&As[r + 8][kk + qc * 2];
                afr[mi][2] = *(const uint32_t*)&As[r][kk + qc * 2 + 8];
                afr[mi][3] = *(const uint32_t*)&As[r + 8][kk + qc * 2 + 8];
            }
#pragma unroll
            for (int nj = 0; nj < 4; nj++) {
                int rj = wx * 32 + nj * 8 + qr;
                bfr[nj][0] = *(const uint32_t*)&Bs[rj][kk + qc * 2];
                bfr[nj][1] = *(const uint32_t*)&Bs[rj][kk + qc * 2 + 8];
            }
#pragma unroll
            for (int mi = 0; mi < 4; mi++)
#pragma unroll
                for (int nj = 0; nj < 4; nj++)
                    mma16816(acc[mi][nj], afr[mi], bfr[nj]);
        }
        __syncthreads();
    }

    // epilogue: out = x + 0.002 * ai
#pragma unroll
    for (int mi = 0; mi < 4; mi++) {
#pragma unroll
        for (int nj = 0; nj < 4; nj++) {
            int c  = wy * 64 + mi * 16 + qr;
            int cj = j0 + wx * 32 + nj * 8 + qc * 2;
            size_t o0 = ((size_t)b * NC + c) * NN + cj;
            size_t o1 = ((size_t)b * NC + c + 8) * NN + cj;
            out[o0]     = x[o0]     + 0.002f * acc[mi][nj][0];
            out[o0 + 1] = x[o0 + 1] + 0.002f * acc[mi][nj][1];
            out[o1]     = x[o1]     + 0.002f * acc[mi][nj][2];
            out[o1 + 1] = x[o1 + 1] + 0.002f * acc[mi][nj][3];
        }
    }
}

// ---------------------------------------------------------------------------
extern "C" void kernel_launch(void* const* d_in, const int* in_sizes, int n_in,
                              void* d_out, int out_size) {
    const float* x = (const float*)d_in[0];
    float* out = (float*)d_out;

    // K0: convert
    {
        size_t n = (size_t)NB * NC * NN;
        int threads = 256;
        int blocks = (int)((n + threads - 1) / threads);
        k_convert<<<blocks, threads>>>(x);
    }
    // K1: scores = F^T F
    {
        dim3 grid(NN / 128, NN / 128, NB);
        k_scores<<<grid, 256>>>();
    }
    // K2: column softmax
    {
        dim3 grid(NN / 128, NB);
        k_softmax<<<grid, 128>>>();
    }
    // K3: ai = F @ attn, residual epilogue
    {
        dim3 grid(NN / 128, NB);
        k_av<<<grid, 256>>>(x, out);
    }
}